// round 5
// baseline (speedup 1.0000x reference)
#include <cuda_runtime.h>
#include <math.h>

#define BB 4
#define VV 8192
#define FF 16384
#define NN 8192
#define SS 16                      // F-chunks per batch
#define CHUNK (FF / SS)            // 1024 faces per block (one smem tile)
#define SCAN_THREADS 128
#define PT 8                       // points per thread (4 f32x2 pairs)
#define PTS_PER_BLOCK (SCAN_THREADS * PT)   // 1024
#define EPS_C 1e-3f
#define WEIGHT_C 1000.0

// ---- scratch (no allocations allowed) ----
__device__ float4 g_c4[BB * FF];        // (cx, cy, cz, |c|^2)
__device__ float4 g_nrm[BB * FF];       // unit normal
__device__ float  g_pscore[BB * SS * NN];
__device__ int    g_pidx[BB * SS * NN];
__device__ double g_acc[2];             // [0]=sum interp^3, [1]=count(interp>0)

// ---- packed f32x2 helpers (sm_103a) ----
__device__ __forceinline__ unsigned long long pack2(float lo, float hi) {
    unsigned long long r;
    asm("mov.b64 %0, {%1, %2};" : "=l"(r) : "f"(lo), "f"(hi));
    return r;
}
__device__ __forceinline__ unsigned long long fma2(unsigned long long a,
                                                   unsigned long long b,
                                                   unsigned long long c) {
    unsigned long long d;
    asm("fma.rn.f32x2 %0, %1, %2, %3;" : "=l"(d) : "l"(a), "l"(b), "l"(c));
    return d;
}
__device__ __forceinline__ void unpack2(unsigned long long v, float& lo, float& hi) {
    asm("mov.b64 {%0, %1}, %2;" : "=f"(lo), "=f"(hi) : "l"(v));
}

// One thread per face: center, |center|^2, unit normal. Thread 0 zeroes accs.
__global__ void faces_kernel(const float* __restrict__ opos,
                             const int* __restrict__ faces) {
    int t = blockIdx.x * blockDim.x + threadIdx.x;
    if (t == 0) { g_acc[0] = 0.0; g_acc[1] = 0.0; }
    if (t >= BB * FF) return;
    int b = t / FF;
    const int* fp = faces + (size_t)t * 3;
    int i0 = fp[0], i1 = fp[1], i2 = fp[2];
    const float* pb = opos + (size_t)b * VV * 3;

    float x0 = __ldg(pb + i0 * 3 + 0), y0 = __ldg(pb + i0 * 3 + 1), z0 = __ldg(pb + i0 * 3 + 2);
    float x1 = __ldg(pb + i1 * 3 + 0), y1 = __ldg(pb + i1 * 3 + 1), z1 = __ldg(pb + i1 * 3 + 2);
    float x2 = __ldg(pb + i2 * 3 + 0), y2 = __ldg(pb + i2 * 3 + 1), z2 = __ldg(pb + i2 * 3 + 2);

    const float third = 1.0f / 3.0f;
    float cx = (x0 + x1 + x2) * third;
    float cy = (y0 + y1 + y2) * third;
    float cz = (z0 + z1 + z2) * third;

    float e1x = x1 - x0, e1y = y1 - y0, e1z = z1 - z0;
    float e2x = x2 - x0, e2y = y2 - y0, e2z = z2 - z0;
    float nx = e1y * e2z - e1z * e2y;
    float ny = e1z * e2x - e1x * e2z;
    float nz = e1x * e2y - e1y * e2x;
    float len = sqrtf(nx * nx + ny * ny + nz * nz);
    float inv = 1.0f / fmaxf(len, 1e-12f);

    g_c4[t]  = make_float4(cx, cy, cz, cx * cx + cy * cy + cz * cz);
    g_nrm[t] = make_float4(nx * inv, ny * inv, nz * inv, 0.0f);
}

// Each block: 1024 points x 1024-face chunk. Faces staged in smem PRE-DUPLICATED
// so f32x2 broadcast pairs come straight out of LDS.128 with no packing MOVs.
// Strict < over ascending j preserves first-index argmin tie-breaking.
__global__ __launch_bounds__(SCAN_THREADS)
void scan_kernel(const float* __restrict__ pred) {
    __shared__ ulonglong2 tA[CHUNK];   // ((x,x),(y,y))
    __shared__ ulonglong2 tB[CHUNK];   // ((z,z),(w,w))

    int b = blockIdx.z;
    int s = blockIdx.y;
    int pbase = blockIdx.x * PTS_PER_BLOCK;
    int tid = threadIdx.x;
    int fbase = s * CHUNK;

    const float4* cbase = g_c4 + (size_t)b * FF + fbase;
    for (int i = tid; i < CHUNK; i += SCAN_THREADS) {
        float4 c = cbase[i];
        tA[i].x = pack2(c.x, c.x);
        tA[i].y = pack2(c.y, c.y);
        tB[i].x = pack2(c.z, c.z);
        tB[i].y = pack2(c.w, c.w);
    }

    // q = -2p, packed per point-pair: lane lo = point k*128+tid (k=2i),
    // lane hi = point (k+1)*128+tid.
    unsigned long long qx2[PT / 2], qy2[PT / 2], qz2[PT / 2];
    float best[PT];
    int bidx[PT];
#pragma unroll
    for (int i = 0; i < PT / 2; i++) {
        int n0 = pbase + (2 * i) * SCAN_THREADS + tid;
        int n1 = n0 + SCAN_THREADS;
        const float* p0 = pred + ((size_t)b * NN + n0) * 3;
        const float* p1 = pred + ((size_t)b * NN + n1) * 3;
        qx2[i] = pack2(-2.0f * __ldg(p0 + 0), -2.0f * __ldg(p1 + 0));
        qy2[i] = pack2(-2.0f * __ldg(p0 + 1), -2.0f * __ldg(p1 + 1));
        qz2[i] = pack2(-2.0f * __ldg(p0 + 2), -2.0f * __ldg(p1 + 2));
        best[2 * i] = 3.4e38f; best[2 * i + 1] = 3.4e38f;
        bidx[2 * i] = 0;       bidx[2 * i + 1] = 0;
    }
    __syncthreads();

#pragma unroll 4
    for (int j = 0; j < CHUNK; j++) {
        ulonglong2 a = tA[j];      // (x,x), (y,y)
        ulonglong2 bb = tB[j];     // (z,z), (w,w)
        int jv = fbase + j;
#pragma unroll
        for (int i = 0; i < PT / 2; i++) {
            // per-lane: ((qz*z + w) + qy*y) + qx*x  — same fma order as R1
            unsigned long long sc = fma2(qz2[i], bb.x, bb.y);
            sc = fma2(qy2[i], a.y, sc);
            sc = fma2(qx2[i], a.x, sc);
            float slo, shi;
            unpack2(sc, slo, shi);
            if (slo < best[2 * i])     { best[2 * i] = slo;     bidx[2 * i] = jv; }
            if (shi < best[2 * i + 1]) { best[2 * i + 1] = shi; bidx[2 * i + 1] = jv; }
        }
    }

    size_t obase = ((size_t)(b * SS + s)) * NN;
#pragma unroll
    for (int k = 0; k < PT; k++) {
        int n = pbase + k * SCAN_THREADS + tid;
        g_pscore[obase + n] = best[k];
        g_pidx[obase + n]   = bidx[k];
    }
}

// Merge chunk partials (ascending chunk order preserves argmin tie-break),
// compute signed distance + hinge, warp-shuffle reduce, 1 atomic pair / block.
__global__ __launch_bounds__(512)
void reduce_kernel(const float* __restrict__ pred) {
    __shared__ double s_loss[16];
    __shared__ double s_cnt[16];

    int t = blockIdx.x * blockDim.x + threadIdx.x;   // [0, BB*NN)
    int b = t / NN;
    int n = t % NN;

    float best = 3.4e38f;
    int bidx = 0;
#pragma unroll
    for (int s = 0; s < SS; s++) {
        size_t o = ((size_t)(b * SS + s)) * NN + n;
        float sc = g_pscore[o];
        int   id = g_pidx[o];
        if (sc < best) { best = sc; bidx = id; }
    }

    float4 c  = g_c4[(size_t)b * FF + bidx];
    float4 nr = g_nrm[(size_t)b * FF + bidx];
    const float* pp = pred + (size_t)t * 3;
    float px = __ldg(pp + 0), py = __ldg(pp + 1), pz = __ldg(pp + 2);
    float d = (px - c.x) * nr.x + (py - c.y) * nr.y + (pz - c.z) * nr.z;
    float interp = fmaxf(EPS_C - d, 0.0f);

    double l = (double)(interp * interp * interp);
    double cc = (interp > 0.0f) ? 1.0 : 0.0;

    int lane = threadIdx.x & 31;
    int warp = threadIdx.x >> 5;
#pragma unroll
    for (int off = 16; off > 0; off >>= 1) {
        l  += __shfl_down_sync(0xffffffffu, l, off);
        cc += __shfl_down_sync(0xffffffffu, cc, off);
    }
    if (lane == 0) { s_loss[warp] = l; s_cnt[warp] = cc; }
    __syncthreads();
    if (warp == 0) {
        double L = (lane < 16) ? s_loss[lane] : 0.0;
        double C = (lane < 16) ? s_cnt[lane] : 0.0;
#pragma unroll
        for (int off = 8; off > 0; off >>= 1) {
            L += __shfl_down_sync(0xffffffffu, L, off);
            C += __shfl_down_sync(0xffffffffu, C, off);
        }
        if (lane == 0) {
            atomicAdd(&g_acc[0], L);
            atomicAdd(&g_acc[1], C);
        }
    }
}

__global__ void finalize_kernel(float* __restrict__ out) {
    out[0] = (float)(g_acc[0] / (double)BB * WEIGHT_C);
    out[1] = (float)(g_acc[1] / (double)(BB * NN));
}

extern "C" void kernel_launch(void* const* d_in, const int* in_sizes, int n_in,
                              void* d_out, int out_size) {
    const float* pred  = (const float*)d_in[0];   // [B,N,3] f32
    const float* opos  = (const float*)d_in[1];   // [B,V,3] f32
    const int*   faces = (const int*)d_in[2];     // [B,F,3] i32
    float* out = (float*)d_out;

    faces_kernel<<<(BB * FF + 255) / 256, 256>>>(opos, faces);
    scan_kernel<<<dim3(NN / PTS_PER_BLOCK, SS, BB), SCAN_THREADS>>>(pred);
    reduce_kernel<<<(BB * NN) / 512, 512>>>(pred);
    finalize_kernel<<<1, 1>>>(out);
}

// round 6
// speedup vs baseline: 1.3086x; 1.3086x over previous
#include <cuda_runtime.h>
#include <math.h>

#define BB 4
#define VV 8192
#define FF 16384
#define NN 8192
#define SS 16                      // F-chunks per batch
#define CHUNK (FF / SS)            // 1024 faces per block (one smem tile)
#define NPAIR (CHUNK / 2)          // 512 face-pairs per tile
#define SCAN_THREADS 128
#define PT 8                       // points per thread
#define PTS_PER_BLOCK (SCAN_THREADS * PT)   // 1024
#define EPS_C 1e-3f
#define WEIGHT_C 1000.0

// ---- scratch (no allocations allowed) ----
__device__ float4 g_c4[BB * FF];        // (cx, cy, cz, |c|^2)
__device__ float4 g_nrm[BB * FF];       // unit normal
__device__ float  g_pscore[BB * SS * NN];
__device__ int    g_pidx[BB * SS * NN]; // EVEN face index of winning pair
__device__ double g_acc[2];             // [0]=sum interp^3, [1]=count(interp>0)
__device__ int    g_done;

// ---- packed f32x2 helpers (sm_103a) ----
__device__ __forceinline__ unsigned long long pack2(float lo, float hi) {
    unsigned long long r;
    asm("mov.b64 %0, {%1, %2};" : "=l"(r) : "f"(lo), "f"(hi));
    return r;
}
__device__ __forceinline__ unsigned long long fma2(unsigned long long a,
                                                   unsigned long long b,
                                                   unsigned long long c) {
    unsigned long long d;
    asm("fma.rn.f32x2 %0, %1, %2, %3;" : "=l"(d) : "l"(a), "l"(b), "l"(c));
    return d;
}
__device__ __forceinline__ void unpack2(unsigned long long v, float& lo, float& hi) {
    asm("mov.b64 {%0, %1}, %2;" : "=f"(lo), "=f"(hi) : "l"(v));
}

// One thread per face: center, |center|^2, unit normal. Thread 0 resets accs.
__global__ void faces_kernel(const float* __restrict__ opos,
                             const int* __restrict__ faces) {
    int t = blockIdx.x * blockDim.x + threadIdx.x;
    if (t == 0) { g_acc[0] = 0.0; g_acc[1] = 0.0; g_done = 0; }
    if (t >= BB * FF) return;
    int b = t / FF;
    const int* fp = faces + (size_t)t * 3;
    int i0 = fp[0], i1 = fp[1], i2 = fp[2];
    const float* pb = opos + (size_t)b * VV * 3;

    float x0 = __ldg(pb + i0 * 3 + 0), y0 = __ldg(pb + i0 * 3 + 1), z0 = __ldg(pb + i0 * 3 + 2);
    float x1 = __ldg(pb + i1 * 3 + 0), y1 = __ldg(pb + i1 * 3 + 1), z1 = __ldg(pb + i1 * 3 + 2);
    float x2 = __ldg(pb + i2 * 3 + 0), y2 = __ldg(pb + i2 * 3 + 1), z2 = __ldg(pb + i2 * 3 + 2);

    const float third = 1.0f / 3.0f;
    float cx = (x0 + x1 + x2) * third;
    float cy = (y0 + y1 + y2) * third;
    float cz = (z0 + z1 + z2) * third;

    float e1x = x1 - x0, e1y = y1 - y0, e1z = z1 - z0;
    float e2x = x2 - x0, e2y = y2 - y0, e2z = z2 - z0;
    float nx = e1y * e2z - e1z * e2y;
    float ny = e1z * e2x - e1x * e2z;
    float nz = e1x * e2y - e1y * e2x;
    float len = sqrtf(nx * nx + ny * ny + nz * nz);
    float inv = 1.0f / fmaxf(len, 1e-12f);

    g_c4[t]  = make_float4(cx, cy, cz, cx * cx + cy * cy + cz * cz);
    g_nrm[t] = make_float4(nx * inv, ny * inv, nz * inv, 0.0f);
}

// Each block: 1024 points x 1024-face chunk. SMEM tile packs FACE PAIRS as
// f32x2 words: tA = ((x_j,x_j+1),(y_j,y_j+1)), tB = ((z...),(w...)). One
// f32x2 FMA chain scores 2 faces; pair-min via FMNMX; only the EVEN index is
// tracked (strict < over ascending pairs). Intra-pair winner is recovered in
// reduce_kernel, preserving exact first-index argmin semantics.
__global__ __launch_bounds__(SCAN_THREADS)
void scan_kernel(const float* __restrict__ pred) {
    __shared__ ulonglong2 tA[NPAIR];   // ((x,x'),(y,y'))
    __shared__ ulonglong2 tB[NPAIR];   // ((z,z'),(w,w'))

    int b = blockIdx.z;
    int s = blockIdx.y;
    int pbase = blockIdx.x * PTS_PER_BLOCK;
    int tid = threadIdx.x;
    int fbase = s * CHUNK;

    const float4* cbase = g_c4 + (size_t)b * FF + fbase;
    for (int m = tid; m < NPAIR; m += SCAN_THREADS) {
        float4 c0 = cbase[2 * m];
        float4 c1 = cbase[2 * m + 1];
        tA[m].x = pack2(c0.x, c1.x);
        tA[m].y = pack2(c0.y, c1.y);
        tB[m].x = pack2(c0.z, c1.z);
        tB[m].y = pack2(c0.w, c1.w);
    }

    // q = -2p broadcast-packed per point.
    unsigned long long qx2[PT], qy2[PT], qz2[PT];
    float best[PT];
    int bidx[PT];
#pragma unroll
    for (int k = 0; k < PT; k++) {
        int n = pbase + k * SCAN_THREADS + tid;
        const float* pp = pred + ((size_t)b * NN + n) * 3;
        float qx = -2.0f * __ldg(pp + 0);
        float qy = -2.0f * __ldg(pp + 1);
        float qz = -2.0f * __ldg(pp + 2);
        qx2[k] = pack2(qx, qx);
        qy2[k] = pack2(qy, qy);
        qz2[k] = pack2(qz, qz);
        best[k] = 3.4e38f;
        bidx[k] = 0;
    }
    __syncthreads();

#pragma unroll 2
    for (int m = 0; m < NPAIR; m++) {
        ulonglong2 a  = tA[m];     // (x,x'), (y,y')
        ulonglong2 bv = tB[m];     // (z,z'), (w,w')
        int jv = fbase + 2 * m;
#pragma unroll
        for (int k = 0; k < PT; k++) {
            // per-lane: ((qz*z + w) + qy*y) + qx*x — same order as before
            unsigned long long sc = fma2(qz2[k], bv.x, bv.y);
            sc = fma2(qy2[k], a.y, sc);
            sc = fma2(qx2[k], a.x, sc);
            float slo, shi;
            unpack2(sc, slo, shi);
            float m2 = fminf(slo, shi);
            if (m2 < best[k]) { best[k] = m2; bidx[k] = jv; }
        }
    }

    size_t obase = ((size_t)(b * SS + s)) * NN;
#pragma unroll
    for (int k = 0; k < PT; k++) {
        int n = pbase + k * SCAN_THREADS + tid;
        g_pscore[obase + n] = best[k];
        g_pidx[obase + n]   = bidx[k];
    }
}

// Merge chunk partials (ascending chunk order preserves argmin tie-break),
// recover intra-pair winner, hinge loss, reduce. Last block finalizes d_out.
__global__ __launch_bounds__(512)
void reduce_kernel(const float* __restrict__ pred, float* __restrict__ out,
                   int nblocks) {
    __shared__ double s_loss[16];
    __shared__ double s_cnt[16];

    int t = blockIdx.x * blockDim.x + threadIdx.x;   // [0, BB*NN)
    int b = t / NN;
    int n = t % NN;

    float best = 3.4e38f;
    int bidx = 0;
#pragma unroll
    for (int s = 0; s < SS; s++) {
        size_t o = ((size_t)(b * SS + s)) * NN + n;
        float sc = g_pscore[o];
        int   id = g_pidx[o];
        if (sc < best) { best = sc; bidx = id; }
    }

    const float* pp = pred + (size_t)t * 3;
    float px = __ldg(pp + 0), py = __ldg(pp + 1), pz = __ldg(pp + 2);
    float qx = -2.0f * px, qy = -2.0f * py, qz = -2.0f * pz;

    // Intra-pair recovery: best equals score(bidx) or score(bidx+1) exactly
    // (FMNMX/select propagate bits; scalar fma.rn == per-lane fma.rn.f32x2).
    // Equality -> lower index, matching JAX first-index argmin on ties.
    float4 cA = g_c4[(size_t)b * FF + bidx];
    float slo = fmaf(qx, cA.x, fmaf(qy, cA.y, fmaf(qz, cA.z, cA.w)));
    int widx = (slo == best) ? bidx : (bidx + 1);

    float4 c  = g_c4[(size_t)b * FF + widx];
    float4 nr = g_nrm[(size_t)b * FF + widx];
    float d = (px - c.x) * nr.x + (py - c.y) * nr.y + (pz - c.z) * nr.z;
    float interp = fmaxf(EPS_C - d, 0.0f);

    double l  = (double)(interp * interp * interp);
    double cc = (interp > 0.0f) ? 1.0 : 0.0;

    int lane = threadIdx.x & 31;
    int warp = threadIdx.x >> 5;
#pragma unroll
    for (int off = 16; off > 0; off >>= 1) {
        l  += __shfl_down_sync(0xffffffffu, l, off);
        cc += __shfl_down_sync(0xffffffffu, cc, off);
    }
    if (lane == 0) { s_loss[warp] = l; s_cnt[warp] = cc; }
    __syncthreads();
    if (warp == 0) {
        double L = (lane < 16) ? s_loss[lane] : 0.0;
        double C = (lane < 16) ? s_cnt[lane] : 0.0;
#pragma unroll
        for (int off = 8; off > 0; off >>= 1) {
            L += __shfl_down_sync(0xffffffffu, L, off);
            C += __shfl_down_sync(0xffffffffu, C, off);
        }
        if (lane == 0) {
            atomicAdd(&g_acc[0], L);
            atomicAdd(&g_acc[1], C);
            __threadfence();
            int done = atomicAdd(&g_done, 1);
            if (done == nblocks - 1) {
                // atomic reads guarantee L2-coherent view of the accumulators
                double totL = atomicAdd(&g_acc[0], 0.0);
                double totC = atomicAdd(&g_acc[1], 0.0);
                out[0] = (float)(totL / (double)BB * WEIGHT_C);
                out[1] = (float)(totC / (double)(BB * NN));
            }
        }
    }
}

extern "C" void kernel_launch(void* const* d_in, const int* in_sizes, int n_in,
                              void* d_out, int out_size) {
    const float* pred  = (const float*)d_in[0];   // [B,N,3] f32
    const float* opos  = (const float*)d_in[1];   // [B,V,3] f32
    const int*   faces = (const int*)d_in[2];     // [B,F,3] i32
    float* out = (float*)d_out;

    faces_kernel<<<(BB * FF + 255) / 256, 256>>>(opos, faces);
    scan_kernel<<<dim3(NN / PTS_PER_BLOCK, SS, BB), SCAN_THREADS>>>(pred);
    int rblocks = (BB * NN) / 512;
    reduce_kernel<<<rblocks, 512>>>(pred, out, rblocks);
}